// round 6
// baseline (speedup 1.0000x reference)
#include <cuda_runtime.h>
#include <cuda_bf16.h>
#include <cstdint>

#define BB 32768
#define FF 128
#define HH 64
#define THREADS 256
#define WARPS 8
#define ROWS_PER_CTA 1024
#define ROWS_STEP 32
#define NCHUNK (BB / ROWS_PER_CTA)        // 32
#define STEPS (ROWS_PER_CTA / ROWS_STEP)  // 32
#define H1S 72                            // bf16 elems per row (144B stride)

// ---- device scratch (no cudaMalloc allowed) ----
__device__ __align__(16) uint32_t g_bfragH[FF * 2048];
__device__ __align__(16) uint32_t g_bfragL[FF * 2048];
__device__ float g_contrib[FF * BB];

__device__ __forceinline__ uint32_t pack_bf16(float v0, float v1) {
    uint32_t r;
    asm("cvt.rn.bf16x2.f32 %0, %1, %2;" : "=r"(r) : "f"(v1), "f"(v0));
    return r;
}
__device__ __forceinline__ uint32_t smem_u32(const void* p) {
    uint32_t a;
    asm("{ .reg .u64 t; cvta.to.shared.u64 t, %1; cvt.u32.u64 %0, t; }" : "=r"(a) : "l"(p));
    return a;
}
__device__ __forceinline__ void mma16816(float* d,
                                         uint32_t a0, uint32_t a1, uint32_t a2, uint32_t a3,
                                         uint32_t b0, uint32_t b1) {
    asm volatile(
        "mma.sync.aligned.m16n8k16.row.col.f32.bf16.bf16.f32 "
        "{%0,%1,%2,%3}, {%4,%5,%6,%7}, {%8,%9}, {%0,%1,%2,%3};"
        : "+f"(d[0]), "+f"(d[1]), "+f"(d[2]), "+f"(d[3])
        : "r"(a0), "r"(a1), "r"(a2), "r"(a3), "r"(b0), "r"(b1));
}
__device__ __forceinline__ void ldsm4(uint32_t* r, uint32_t addr) {
    asm volatile("ldmatrix.sync.aligned.m8n8.x4.shared.b16 {%0,%1,%2,%3}, [%4];"
                 : "=r"(r[0]), "=r"(r[1]), "=r"(r[2]), "=r"(r[3]) : "r"(addr));
}
__device__ __forceinline__ void sts128(uint32_t addr, uint32_t r0, uint32_t r1,
                                       uint32_t r2, uint32_t r3) {
    asm volatile("st.shared.v4.b32 [%0], {%1,%2,%3,%4};"
                 :: "r"(addr), "r"(r0), "r"(r1), "r"(r2), "r"(r3) : "memory");
}

// -------- prep: split w2 into bf16 hi/lo packed in m16n8k16 B-fragment order --------
__global__ void prep_kernel(const float* __restrict__ w2) {
    int e = blockIdx.x * blockDim.x + threadIdx.x;   // < FF*2048
    int lane = e & 31;
    int i = (e >> 5) & 1;
    int q = (e >> 6) & 3;
    int w = (e >> 8) & 7;
    int f = e >> 11;
    int k0 = q * 16 + (lane & 3) * 2 + 8 * i;
    int g = w * 8 + (lane >> 2);
    float v0 = w2[f * 4096 + k0 * 64 + g];
    float v1 = w2[f * 4096 + (k0 + 1) * 64 + g];
    uint32_t hi = pack_bf16(v0, v1);
    float r0 = v0 - __uint_as_float(hi << 16);
    float r1 = v1 - __uint_as_float(hi & 0xFFFF0000u);
    g_bfragH[e] = hi;
    g_bfragL[e] = pack_bf16(r0, r1);
}

// -------- main kernel (pipelined, split accumulator chains) --------
__global__ __launch_bounds__(THREADS)
void mlp_mma_kernel(const float* __restrict__ x,
                    const float* __restrict__ w1,
                    const float* __restrict__ b1,
                    const float* __restrict__ b2,
                    const float* __restrict__ w3,
                    const float* __restrict__ b3) {
    __shared__ __align__(16) __nv_bfloat16 h1h[2][ROWS_STEP * H1S];
    __shared__ __align__(16) __nv_bfloat16 h1l[2][ROWS_STEP * H1S];
    __shared__ float wsum[2][WARPS][2][ROWS_STEP];   // [buf][warp][c-part][row]
    __shared__ float w1s[HH], b1s[HH], b2s[HH], w3s[HH];

    const int tid = threadIdx.x;
    const int warp = tid >> 5, lane = tid & 31;
    const int f = blockIdx.y;
    const int row0 = blockIdx.x * ROWS_PER_CTA;

    if (tid < HH) {
        w1s[tid] = w1[f * HH + tid];
        b1s[tid] = b1[f * HH + tid];
        b2s[tid] = b2[f * HH + tid];
        w3s[tid] = w3[f * HH + tid];
    }
    const float b3f = __ldg(b3 + f);

    // B fragments in registers (warp owns n-slice warp*8..+8)
    uint32_t bh[4][2], bl[4][2];
    {
        int base = f * 2048 + warp * 256 + lane;
        #pragma unroll
        for (int q = 0; q < 4; ++q)
            #pragma unroll
            for (int i = 0; i < 2; ++i) {
                bh[q][i] = g_bfragH[base + q * 64 + i * 32];
                bl[q][i] = g_bfragL[base + q * 64 + i * 32];
            }
    }

    const int m = lane >> 2, c = lane & 3;
    const int n0 = warp * 8 + 2 * c;
    const int hr = tid >> 3;
    const int hcb = (tid & 7) * 16;
    const int hc = (tid & 7) * 8;

    const uint32_t bufH[2] = {smem_u32(h1h[0]), smem_u32(h1h[1])};
    const uint32_t bufL[2] = {smem_u32(h1l[0]), smem_u32(h1l[1])};
    const uint32_t lmoff = (uint32_t)(((lane & 7) + ((lane >> 3) & 1) * 8) * (H1S * 2)
                                      + (lane >> 4) * 16);
    const uint32_t stoff = (uint32_t)(hr * (H1S * 2) + hcb);

    __syncthreads();
    const float4 wa = *(const float4*)(w1s + hc);
    const float4 wb = *(const float4*)(w1s + hc + 4);
    const float4 ba = *(const float4*)(b1s + hc);
    const float4 bb = *(const float4*)(b1s + hc + 4);

    auto h1_store = [&](float xv, int buf) {
        float v0 = fmaxf(fmaf(xv, wa.x, ba.x), 0.f);
        float v1 = fmaxf(fmaf(xv, wa.y, ba.y), 0.f);
        float v2 = fmaxf(fmaf(xv, wa.z, ba.z), 0.f);
        float v3 = fmaxf(fmaf(xv, wa.w, ba.w), 0.f);
        float v4 = fmaxf(fmaf(xv, wb.x, bb.x), 0.f);
        float v5 = fmaxf(fmaf(xv, wb.y, bb.y), 0.f);
        float v6 = fmaxf(fmaf(xv, wb.z, bb.z), 0.f);
        float v7 = fmaxf(fmaf(xv, wb.w, bb.w), 0.f);
        uint32_t h0 = pack_bf16(v0, v1), h1v = pack_bf16(v2, v3);
        uint32_t h2 = pack_bf16(v4, v5), h3 = pack_bf16(v6, v7);
        uint32_t l0 = pack_bf16(v0 - __uint_as_float(h0 << 16),
                                v1 - __uint_as_float(h0 & 0xFFFF0000u));
        uint32_t l1 = pack_bf16(v2 - __uint_as_float(h1v << 16),
                                v3 - __uint_as_float(h1v & 0xFFFF0000u));
        uint32_t l2 = pack_bf16(v4 - __uint_as_float(h2 << 16),
                                v5 - __uint_as_float(h2 & 0xFFFF0000u));
        uint32_t l3 = pack_bf16(v6 - __uint_as_float(h3 << 16),
                                v7 - __uint_as_float(h3 & 0xFFFF0000u));
        sts128(bufH[buf] + stoff, h0, h1v, h2, h3);
        sts128(bufL[buf] + stoff, l0, l1, l2, l3);
    };

    // prologue
    float xv0 = __ldg(x + (size_t)(row0 + hr) * FF + f);
    h1_store(xv0, 0);
    float xv1 = __ldg(x + (size_t)(row0 + ROWS_STEP + hr) * FF + f);
    __syncthreads();

    for (int stp = 0; stp < STEPS; ++stp) {
        const int cur = stp & 1;

        // (a) previous step's contrib write (overlapped)
        if (stp > 0 && tid < ROWS_STEP) {
            const float* ws = &wsum[cur ^ 1][0][0][tid];
            float s = 0.f;
            #pragma unroll
            for (int i = 0; i < 16; ++i) s += ws[i * ROWS_STEP];
            g_contrib[f * BB + row0 + (stp - 1) * ROWS_STEP + tid] = s + b3f;
        }

        // (b) next step's layer-1 + STS into the other buffer
        if (stp + 1 < STEPS) {
            h1_store(xv1, cur ^ 1);
            if (stp + 2 < STEPS)
                xv1 = __ldg(x + (size_t)(row0 + (stp + 2) * ROWS_STEP + hr) * FF + f);
        }

        // (c) MMA block: 6 independent accumulator chains of length 4
        float dhh[2][4] = {{0.f,0.f,0.f,0.f},{0.f,0.f,0.f,0.f}};
        float dhl[2][4] = {{0.f,0.f,0.f,0.f},{0.f,0.f,0.f,0.f}};
        float dlh[2][4] = {{0.f,0.f,0.f,0.f},{0.f,0.f,0.f,0.f}};
        {
            const uint32_t t0h = bufH[cur] + lmoff;
            const uint32_t t1h = t0h + (uint32_t)(16 * H1S * 2);
            const uint32_t t0l = bufL[cur] + lmoff;
            const uint32_t t1l = t0l + (uint32_t)(16 * H1S * 2);
            #pragma unroll
            for (int q = 0; q < 4; ++q) {
                uint32_t a0h[4], a1h[4], a0l[4], a1l[4];
                ldsm4(a0h, t0h + q * 32);
                ldsm4(a1h, t1h + q * 32);
                ldsm4(a0l, t0l + q * 32);
                ldsm4(a1l, t1l + q * 32);
                mma16816(dhh[0], a0h[0], a0h[1], a0h[2], a0h[3], bh[q][0], bh[q][1]);
                mma16816(dhh[1], a1h[0], a1h[1], a1h[2], a1h[3], bh[q][0], bh[q][1]);
                mma16816(dhl[0], a0h[0], a0h[1], a0h[2], a0h[3], bl[q][0], bl[q][1]);
                mma16816(dhl[1], a1h[0], a1h[1], a1h[2], a1h[3], bl[q][0], bl[q][1]);
                mma16816(dlh[0], a0l[0], a0l[1], a0l[2], a0l[3], bh[q][0], bh[q][1]);
                mma16816(dlh[1], a1l[0], a1l[1], a1l[2], a1l[3], bh[q][0], bh[q][1]);
            }
        }

        // (d) epilogue: combine chains, relu(.+b2).w3, single shfl, 2 partials
        {
            float B0 = b2s[n0], B1 = b2s[n0 + 1];
            float W0 = w3s[n0], W1 = w3s[n0 + 1];
            #pragma unroll
            for (int t = 0; t < 2; ++t) {
                float d0 = (dhh[t][0] + dhl[t][0]) + dlh[t][0];
                float d1 = (dhh[t][1] + dhl[t][1]) + dlh[t][1];
                float d2 = (dhh[t][2] + dhl[t][2]) + dlh[t][2];
                float d3 = (dhh[t][3] + dhl[t][3]) + dlh[t][3];
                float e0 = fmaf(fmaxf(d0 + B0, 0.f), W0, fmaxf(d1 + B1, 0.f) * W1);
                float e1 = fmaf(fmaxf(d2 + B0, 0.f), W0, fmaxf(d3 + B1, 0.f) * W1);
                e0 += __shfl_xor_sync(0xFFFFFFFFu, e0, 2);
                e1 += __shfl_xor_sync(0xFFFFFFFFu, e1, 2);
                if (c < 2) {
                    wsum[cur][warp][c][t * 16 + m] = e0;
                    wsum[cur][warp][c][t * 16 + 8 + m] = e1;
                }
            }
        }

        // (e) single barrier: publishes wsum AND next buffer's h1
        __syncthreads();
    }

    // tail
    if (tid < ROWS_STEP) {
        const float* ws = &wsum[(STEPS - 1) & 1][0][0][tid];
        float s = 0.f;
        #pragma unroll
        for (int i = 0; i < 16; ++i) s += ws[i * ROWS_STEP];
        g_contrib[f * BB + row0 + (STEPS - 1) * ROWS_STEP + tid] = s + b3f;
    }
}

__global__ void finalize_kernel(const float* __restrict__ bias,
                                float* __restrict__ out) {
    int b = blockIdx.x * blockDim.x + threadIdx.x;
    if (b >= BB) return;
    float l = bias[0];
    #pragma unroll 16
    for (int f = 0; f < FF; ++f) l += g_contrib[f * BB + b];
    float p = 1.0f / (1.0f + expf(-l));
    out[2 * b + 0] = 1.0f - p;
    out[2 * b + 1] = p;
}

extern "C" void kernel_launch(void* const* d_in, const int* in_sizes, int n_in,
                              void* d_out, int out_size) {
    const float* x    = (const float*)d_in[0];
    const float* w1   = (const float*)d_in[1];
    const float* b1   = (const float*)d_in[2];
    const float* w2   = (const float*)d_in[3];
    const float* b2   = (const float*)d_in[4];
    const float* w3   = (const float*)d_in[5];
    const float* b3   = (const float*)d_in[6];
    const float* bias = (const float*)d_in[7];
    float* out = (float*)d_out;

    prep_kernel<<<(FF * 2048) / 256, 256>>>(w2);
    dim3 grid(NCHUNK, FF);   // 32 x 128 = 4096 CTAs
    mlp_mma_kernel<<<grid, THREADS>>>(x, w1, b1, b2, w3, b3);
    finalize_kernel<<<BB / 256, 256>>>(bias, out);
}

// round 7
// speedup vs baseline: 3.0806x; 3.0806x over previous
#include <cuda_runtime.h>
#include <cstdint>

#define BB 32768
#define FF 128
#define HH 64
#define NMAX 4224   // 64 L1 boundaries + 65*64 L2 kinks (worst case)

// ---- device scratch (no cudaMalloc allowed) ----
__device__ float  g_tsort[FF * HH];
__device__ int    stage_n[FF * 65];
__device__ float  stage_kinks[FF * 65 * 64];
__device__ float2 stage_SI[FF * 65 * 65];
__device__ float  g_X[FF * NMAX];
__device__ float2 g_SI[FF * (NMAX + 1)];
__device__ int    g_N[FF];
__device__ float  g_xT[FF * BB];
__device__ float  g_contrib[FF * BB];

__device__ __forceinline__ float finf() { return __int_as_float(0x7f800000); }

// ---- K0: per-feature sorted layer-1 breakpoints t_h = -b1/w1 ----
__global__ void sort_t_kernel(const float* __restrict__ w1, const float* __restrict__ b1) {
    __shared__ float t[HH];
    const int f = blockIdx.x, h = threadIdx.x;
    float w = w1[f * HH + h], b = b1[f * HH + h];
    float tv;
    if (w == 0.f) tv = finf();
    else { tv = -b / w; if (tv != tv) tv = finf(); }
    t[h] = tv;
    __syncthreads();
    for (int p = 0; p < HH; ++p) {          // odd-even transposition sort
        int i = 2 * h + (p & 1);
        if (i + 1 < HH) {
            float a = t[i], c = t[i + 1];
            if (c < a) { t[i] = c; t[i + 1] = a; }
        }
        __syncthreads();
    }
    g_tsort[f * HH + h] = t[h];
}

// ---- K1: per (feature f, L1-segment s): in-segment kinks + prefix slopes ----
__global__ void build_kernel(const float* __restrict__ w1, const float* __restrict__ b1,
                             const float* __restrict__ w2, const float* __restrict__ b2,
                             const float* __restrict__ w3, const float* __restrict__ b3) {
    const int s = blockIdx.x;   // 0..64
    const int f = blockIdx.y;
    const int g = threadIdx.x;  // 0..63
    __shared__ float w1s[HH], b1s[HH];
    __shared__ float kk[HH], dsv[HH], div_[HH];
    __shared__ double red[HH], ps[HH], pi[HH];
    __shared__ float Ts[HH + 2];
    __shared__ double sS0, sI0;

    w1s[g] = w1[f * HH + g];
    b1s[g] = b1[f * HH + g];
    Ts[g + 1] = g_tsort[f * HH + g];
    if (g == 0) { Ts[0] = -finf(); Ts[HH + 1] = finf(); }
    __syncthreads();

    const float Tlo = Ts[s], Thi = Ts[s + 1];
    const bool loI = isinf(Tlo), hiI = isinf(Thi);
    float xm;
    if (!loI && !hiI)      xm = 0.5f * Tlo + 0.5f * Thi;
    else if (loI && hiI)   xm = 0.f;
    else if (loI)          xm = Thi - 1.f;
    else                   xm = Tlo + 1.f;

    // alpha_g, beta'_g for this segment (active set fixed within segment)
    float a = 0.f, be = 0.f;
    #pragma unroll 8
    for (int h = 0; h < HH; ++h) {
        if (fmaf(xm, w1s[h], b1s[h]) > 0.f) {   // uniform branch over block
            float w2v = __ldg(w2 + f * HH * HH + h * HH + g);
            a  = fmaf(w1s[h], w2v, a);
            be = fmaf(b1s[h], w2v, be);
        }
    }
    be += __ldg(b2 + f * HH + g);
    const float w3v = __ldg(w3 + f * HH + g);

    // classify relu_g within (Tlo, Thi)
    bool ev = false, baseAct = false;
    float kink = finf(), dsl = 0.f, din = 0.f;
    if (a > 0.f) {
        float xs = -be / a;
        if (xs <= Tlo) baseAct = true;                       // active throughout
        else if (xs < Thi) { ev = true; kink = xs; dsl = w3v * a; din = w3v * be; }
    } else if (a < 0.f) {
        float xs = -be / a;
        if (xs >= Thi) baseAct = true;                       // active throughout
        else if (xs > Tlo) { ev = true; baseAct = true;      // active at start, turns off
                             kink = xs; dsl = -w3v * a; din = -w3v * be; }
    } else {
        if (be > 0.f) baseAct = true;                        // constant contribution
    }

    // S0 = sum of active w3*alpha at segment start (fp64 reduce)
    red[g] = baseAct ? (double)(w3v * a) : 0.0;
    __syncthreads();
    for (int o = 32; o > 0; o >>= 1) { if (g < o) red[g] += red[g + o]; __syncthreads(); }
    if (g == 0) sS0 = red[0];
    __syncthreads();
    red[g] = baseAct ? (double)(w3v * be) : 0.0;
    __syncthreads();
    for (int o = 32; o > 0; o >>= 1) { if (g < o) red[g] += red[g + o]; __syncthreads(); }
    if (g == 0) sI0 = red[0] + (double)__ldg(b3 + f);        // fold b3 into intercept
    const int n = __syncthreads_count(ev ? 1 : 0);

    kk[g] = kink; dsv[g] = dsl; div_[g] = din;
    __syncthreads();

    // bitonic sort 64 (keys kk asc; non-events padded +inf)
    for (int k = 2; k <= HH; k <<= 1)
        for (int j = k >> 1; j > 0; j >>= 1) {
            int ixj = g ^ j;
            if (ixj > g) {
                bool up = ((g & k) == 0);
                if ((kk[g] > kk[ixj]) == up) {
                    float t0;
                    t0 = kk[g];   kk[g] = kk[ixj];     kk[ixj] = t0;
                    t0 = dsv[g];  dsv[g] = dsv[ixj];   dsv[ixj] = t0;
                    t0 = div_[g]; div_[g] = div_[ixj]; div_[ixj] = t0;
                }
            }
            __syncthreads();
        }

    // inclusive prefix sums of deltas (fp64)
    ps[g] = (double)dsv[g]; pi[g] = (double)div_[g];
    __syncthreads();
    for (int o = 1; o < HH; o <<= 1) {
        double vs = (g >= o) ? ps[g - o] : 0.0;
        double vi = (g >= o) ? pi[g - o] : 0.0;
        __syncthreads();
        ps[g] += vs; pi[g] += vi;
        __syncthreads();
    }

    const int fs = f * 65 + s;
    if (g == 0) {
        stage_n[fs] = n;
        stage_SI[fs * 65] = make_float2((float)sS0, (float)sI0);
    }
    if (g < n) {
        stage_kinks[fs * 64 + g] = kk[g];
        stage_SI[fs * 65 + g + 1] =
            make_float2((float)(sS0 + ps[g]), (float)(sI0 + pi[g]));
    }
}

// ---- K2: concatenate per-segment tables (naturally globally sorted) ----
__global__ void compact_kernel() {
    const int f = blockIdx.x;
    const int tid = threadIdx.x;
    __shared__ int offX[66];
    __shared__ int nsh[65];
    if (tid < 65) nsh[tid] = stage_n[f * 65 + tid];
    __syncthreads();
    if (tid == 0) {
        int c = 0;
        for (int s = 0; s < 65; ++s) { offX[s] = c; c += nsh[s] + (s < 64 ? 1 : 0); }
        offX[65] = c;
        g_N[f] = c;
    }
    __syncthreads();
    for (int s = 0; s < 65; ++s) {
        const int n = nsh[s], ox = offX[s], fs = f * 65 + s;
        for (int j = tid; j < n; j += blockDim.x)
            g_X[f * NMAX + ox + j] = stage_kinks[fs * 64 + j];
        for (int j = tid; j <= n; j += blockDim.x)
            g_SI[f * (NMAX + 1) + ox + j] = stage_SI[fs * 65 + j];
        if (s < 64 && tid == 0)
            g_X[f * NMAX + ox + n] = g_tsort[f * HH + s];
    }
}

// ---- K3: transpose x (B,F) -> (F,B) for coalesced eval ----
__global__ void xT_kernel(const float* __restrict__ x) {
    __shared__ float tile[32][33];
    const int bb = blockIdx.x * 32, ff = blockIdx.y * 32;
    const int tx = threadIdx.x, ty = threadIdx.y;
    #pragma unroll
    for (int i = ty; i < 32; i += 8)
        tile[i][tx] = x[(size_t)(bb + i) * FF + ff + tx];
    __syncthreads();
    #pragma unroll
    for (int i = ty; i < 32; i += 8)
        g_xT[(size_t)(ff + i) * BB + bb + tx] = tile[tx][i];
}

// ---- K4: eval — binary search + 1 FMA per (b,f) ----
__global__ __launch_bounds__(256) void eval_kernel() {
    __shared__ float Xs[NMAX];
    const int f = blockIdx.y;
    const int N = g_N[f];
    for (int i = threadIdx.x; i < N; i += 256) Xs[i] = g_X[f * NMAX + i];
    __syncthreads();
    const float2* SI = g_SI + (size_t)f * (NMAX + 1);
    const float* xp = g_xT + (size_t)f * BB + blockIdx.x * 4096;
    float* cp = g_contrib + (size_t)f * BB + blockIdx.x * 4096;
    for (int r = threadIdx.x; r < 4096; r += 256) {
        float xv = __ldg(xp + r);
        int lo = 0, len = N;
        while (len > 0) {                       // upper_bound
            int half = len >> 1;
            if (Xs[lo + half] <= xv) { lo += half + 1; len -= half + 1; }
            else len = half;
        }
        float2 si = __ldg(SI + lo);
        cp[r] = fmaf(si.x, xv, si.y);
    }
}

// ---- K5: finalize (proven from earlier rounds) ----
__global__ void finalize_kernel(const float* __restrict__ bias,
                                float* __restrict__ out) {
    int b = blockIdx.x * blockDim.x + threadIdx.x;
    if (b >= BB) return;
    float l = bias[0];
    #pragma unroll 16
    for (int f = 0; f < FF; ++f) l += g_contrib[f * BB + b];
    float p = 1.0f / (1.0f + expf(-l));
    out[2 * b + 0] = 1.0f - p;
    out[2 * b + 1] = p;
}

extern "C" void kernel_launch(void* const* d_in, const int* in_sizes, int n_in,
                              void* d_out, int out_size) {
    const float* x    = (const float*)d_in[0];
    const float* w1   = (const float*)d_in[1];
    const float* b1   = (const float*)d_in[2];
    const float* w2   = (const float*)d_in[3];
    const float* b2   = (const float*)d_in[4];
    const float* w3   = (const float*)d_in[5];
    const float* b3   = (const float*)d_in[6];
    const float* bias = (const float*)d_in[7];
    float* out = (float*)d_out;

    sort_t_kernel<<<FF, HH>>>(w1, b1);
    build_kernel<<<dim3(65, FF), HH>>>(w1, b1, w2, b2, w3, b3);
    compact_kernel<<<FF, 256>>>();
    xT_kernel<<<dim3(BB / 32, FF / 32), dim3(32, 8)>>>(x);
    eval_kernel<<<dim3(8, FF), 256>>>();
    finalize_kernel<<<BB / 256, 256>>>(bias, out);
}

// round 8
// speedup vs baseline: 3.0884x; 1.0025x over previous
#include <cuda_runtime.h>
#include <cstdint>

#define BB 32768
#define FF 128
#define HH 64
#define NMAX 4224   // 64 L1 boundaries + 65*64 L2 kinks (worst case)

// ---- device scratch (no cudaMalloc allowed) ----
__device__ float  g_tsort[FF * HH];
__device__ int    stage_n[FF * 65];
__device__ float  stage_kinks[FF * 65 * 64];
__device__ float2 stage_SI[FF * 65 * 65];
__device__ float  g_X[FF * NMAX];
__device__ float2 g_SI[FF * (NMAX + 1)];
__device__ int    g_N[FF];
__device__ float  g_xT[FF * BB];
__device__ float  g_contrib[FF * BB];

__device__ __forceinline__ float finf() { return __int_as_float(0x7f800000); }

// ---- K0: per-feature sorted layer-1 breakpoints t_h = -b1/w1 ----
__global__ void sort_t_kernel(const float* __restrict__ w1, const float* __restrict__ b1) {
    __shared__ float t[HH];
    const int f = blockIdx.x, h = threadIdx.x;
    float w = w1[f * HH + h], b = b1[f * HH + h];
    float tv;
    if (w == 0.f) tv = finf();
    else { tv = -b / w; if (tv != tv) tv = finf(); }
    t[h] = tv;
    __syncthreads();
    for (int p = 0; p < HH; ++p) {          // odd-even transposition sort
        int i = 2 * h + (p & 1);
        if (i + 1 < HH) {
            float a = t[i], c = t[i + 1];
            if (c < a) { t[i] = c; t[i + 1] = a; }
        }
        __syncthreads();
    }
    g_tsort[f * HH + h] = t[h];
}

// ---- K1: per (feature f, L1-segment s): in-segment kinks + prefix slopes ----
__global__ void build_kernel(const float* __restrict__ w1, const float* __restrict__ b1,
                             const float* __restrict__ w2, const float* __restrict__ b2,
                             const float* __restrict__ w3, const float* __restrict__ b3) {
    const int s = blockIdx.x;   // 0..64
    const int f = blockIdx.y;
    const int g = threadIdx.x;  // 0..63
    __shared__ float w1s[HH], b1s[HH];
    __shared__ float kk[HH], dsv[HH], div_[HH];
    __shared__ double red[HH], ps[HH], pi[HH];
    __shared__ float Ts[HH + 2];
    __shared__ double sS0, sI0;

    w1s[g] = w1[f * HH + g];
    b1s[g] = b1[f * HH + g];
    Ts[g + 1] = g_tsort[f * HH + g];
    if (g == 0) { Ts[0] = -finf(); Ts[HH + 1] = finf(); }
    __syncthreads();

    const float Tlo = Ts[s], Thi = Ts[s + 1];
    const bool loI = isinf(Tlo), hiI = isinf(Thi);
    float xm;
    if (!loI && !hiI)      xm = 0.5f * Tlo + 0.5f * Thi;
    else if (loI && hiI)   xm = 0.f;
    else if (loI)          xm = Thi - 1.f;
    else                   xm = Tlo + 1.f;

    // alpha_g, beta'_g for this segment (active set fixed within segment)
    float a = 0.f, be = 0.f;
    #pragma unroll 8
    for (int h = 0; h < HH; ++h) {
        if (fmaf(xm, w1s[h], b1s[h]) > 0.f) {   // uniform branch over block
            float w2v = __ldg(w2 + f * HH * HH + h * HH + g);
            a  = fmaf(w1s[h], w2v, a);
            be = fmaf(b1s[h], w2v, be);
        }
    }
    be += __ldg(b2 + f * HH + g);
    const float w3v = __ldg(w3 + f * HH + g);

    // classify relu_g within (Tlo, Thi)
    bool ev = false, baseAct = false;
    float kink = finf(), dsl = 0.f, din = 0.f;
    if (a > 0.f) {
        float xs = -be / a;
        if (xs <= Tlo) baseAct = true;                       // active throughout
        else if (xs < Thi) { ev = true; kink = xs; dsl = w3v * a; din = w3v * be; }
    } else if (a < 0.f) {
        float xs = -be / a;
        if (xs >= Thi) baseAct = true;                       // active throughout
        else if (xs > Tlo) { ev = true; baseAct = true;      // active at start, turns off
                             kink = xs; dsl = -w3v * a; din = -w3v * be; }
    } else {
        if (be > 0.f) baseAct = true;                        // constant contribution
    }

    // S0 = sum of active w3*alpha at segment start (fp64 reduce)
    red[g] = baseAct ? (double)(w3v * a) : 0.0;
    __syncthreads();
    for (int o = 32; o > 0; o >>= 1) { if (g < o) red[g] += red[g + o]; __syncthreads(); }
    if (g == 0) sS0 = red[0];
    __syncthreads();
    red[g] = baseAct ? (double)(w3v * be) : 0.0;
    __syncthreads();
    for (int o = 32; o > 0; o >>= 1) { if (g < o) red[g] += red[g + o]; __syncthreads(); }
    if (g == 0) sI0 = red[0] + (double)__ldg(b3 + f);        // fold b3 into intercept
    const int n = __syncthreads_count(ev ? 1 : 0);

    kk[g] = kink; dsv[g] = dsl; div_[g] = din;
    __syncthreads();

    // bitonic sort 64 (keys kk asc; non-events padded +inf)
    for (int k = 2; k <= HH; k <<= 1)
        for (int j = k >> 1; j > 0; j >>= 1) {
            int ixj = g ^ j;
            if (ixj > g) {
                bool up = ((g & k) == 0);
                if ((kk[g] > kk[ixj]) == up) {
                    float t0;
                    t0 = kk[g];   kk[g] = kk[ixj];     kk[ixj] = t0;
                    t0 = dsv[g];  dsv[g] = dsv[ixj];   dsv[ixj] = t0;
                    t0 = div_[g]; div_[g] = div_[ixj]; div_[ixj] = t0;
                }
            }
            __syncthreads();
        }

    // inclusive prefix sums of deltas (fp64)
    ps[g] = (double)dsv[g]; pi[g] = (double)div_[g];
    __syncthreads();
    for (int o = 1; o < HH; o <<= 1) {
        double vs = (g >= o) ? ps[g - o] : 0.0;
        double vi = (g >= o) ? pi[g - o] : 0.0;
        __syncthreads();
        ps[g] += vs; pi[g] += vi;
        __syncthreads();
    }

    const int fs = f * 65 + s;
    if (g == 0) {
        stage_n[fs] = n;
        stage_SI[fs * 65] = make_float2((float)sS0, (float)sI0);
    }
    if (g < n) {
        stage_kinks[fs * 64 + g] = kk[g];
        stage_SI[fs * 65 + g + 1] =
            make_float2((float)(sS0 + ps[g]), (float)(sI0 + pi[g]));
    }
}

// ---- K2: concatenate per-segment tables (naturally globally sorted) ----
__global__ void compact_kernel() {
    const int f = blockIdx.x;
    const int tid = threadIdx.x;
    __shared__ int offX[66];
    __shared__ int nsh[65];
    if (tid < 65) nsh[tid] = stage_n[f * 65 + tid];
    __syncthreads();
    if (tid == 0) {
        int c = 0;
        for (int s = 0; s < 65; ++s) { offX[s] = c; c += nsh[s] + (s < 64 ? 1 : 0); }
        offX[65] = c;
        g_N[f] = c;
    }
    __syncthreads();
    for (int s = 0; s < 65; ++s) {
        const int n = nsh[s], ox = offX[s], fs = f * 65 + s;
        for (int j = tid; j < n; j += blockDim.x)
            g_X[f * NMAX + ox + j] = stage_kinks[fs * 64 + j];
        for (int j = tid; j <= n; j += blockDim.x)
            g_SI[f * (NMAX + 1) + ox + j] = stage_SI[fs * 65 + j];
        if (s < 64 && tid == 0)
            g_X[f * NMAX + ox + n] = g_tsort[f * HH + s];
    }
}

// ---- K3: transpose x (B,F) -> (F,B) for coalesced eval ----
__global__ void xT_kernel(const float* __restrict__ x) {
    __shared__ float tile[32][33];
    const int bb = blockIdx.x * 32, ff = blockIdx.y * 32;
    const int tx = threadIdx.x, ty = threadIdx.y;
    #pragma unroll
    for (int i = ty; i < 32; i += 8)
        tile[i][tx] = x[(size_t)(bb + i) * FF + ff + tx];
    __syncthreads();
    #pragma unroll
    for (int i = ty; i < 32; i += 8)
        g_xT[(size_t)(ff + i) * BB + bb + tx] = tile[tx][i];
}

// ---- K4: eval — binary search + 1 FMA per (b,f) ----
__global__ __launch_bounds__(256) void eval_kernel() {
    __shared__ float Xs[NMAX];
    const int f = blockIdx.y;
    const int N = g_N[f];
    for (int i = threadIdx.x; i < N; i += 256) Xs[i] = g_X[f * NMAX + i];
    __syncthreads();
    const float2* SI = g_SI + (size_t)f * (NMAX + 1);
    const float* xp = g_xT + (size_t)f * BB + blockIdx.x * 4096;
    float* cp = g_contrib + (size_t)f * BB + blockIdx.x * 4096;
    for (int r = threadIdx.x; r < 4096; r += 256) {
        float xv = __ldg(xp + r);
        int lo = 0, len = N;
        while (len > 0) {                       // upper_bound
            int half = len >> 1;
            if (Xs[lo + half] <= xv) { lo += half + 1; len -= half + 1; }
            else len = half;
        }
        float2 si = __ldg(SI + lo);
        cp[r] = fmaf(si.x, xv, si.y);
    }
}

// ---- K5: finalize (proven from earlier rounds) ----
__global__ void finalize_kernel(const float* __restrict__ bias,
                                float* __restrict__ out) {
    int b = blockIdx.x * blockDim.x + threadIdx.x;
    if (b >= BB) return;
    float l = bias[0];
    #pragma unroll 16
    for (int f = 0; f < FF; ++f) l += g_contrib[f * BB + b];
    float p = 1.0f / (1.0f + expf(-l));
    out[2 * b + 0] = 1.0f - p;
    out[2 * b + 1] = p;
}

extern "C" void kernel_launch(void* const* d_in, const int* in_sizes, int n_in,
                              void* d_out, int out_size) {
    const float* x    = (const float*)d_in[0];
    const float* w1   = (const float*)d_in[1];
    const float* b1   = (const float*)d_in[2];
    const float* w2   = (const float*)d_in[3];
    const float* b2   = (const float*)d_in[4];
    const float* w3   = (const float*)d_in[5];
    const float* b3   = (const float*)d_in[6];
    const float* bias = (const float*)d_in[7];
    float* out = (float*)d_out;

    sort_t_kernel<<<FF, HH>>>(w1, b1);
    build_kernel<<<dim3(65, FF), HH>>>(w1, b1, w2, b2, w3, b3);
    compact_kernel<<<FF, 256>>>();
    xT_kernel<<<dim3(BB / 32, FF / 32), dim3(32, 8)>>>(x);
    eval_kernel<<<dim3(8, FF), 256>>>();
    finalize_kernel<<<BB / 256, 256>>>(bias, out);
}

// round 9
// speedup vs baseline: 3.1120x; 1.0076x over previous
#include <cuda_runtime.h>
#include <cstdint>

#define BB 32768
#define FF 128
#define HH 64
#define NMAX 4224   // 64 L1 boundaries + 65*64 L2 kinks (worst case)

// ---- device scratch (no cudaMalloc allowed) ----
__device__ float  g_tsort[FF * HH];
__device__ int    stage_n[FF * 65];
__device__ float  stage_kinks[FF * 65 * 64];
__device__ float2 stage_SI[FF * 65 * 65];
__device__ float  g_X[FF * NMAX];
__device__ float2 g_SI[FF * (NMAX + 1)];
__device__ int    g_N[FF];
__device__ float  g_xT[FF * BB];
__device__ float  g_contrib[FF * BB];

__device__ __forceinline__ float finf() { return __int_as_float(0x7f800000); }

// ---- K0: per-feature sorted layer-1 breakpoints t_h = -b1/w1 ----
__global__ void sort_t_kernel(const float* __restrict__ w1, const float* __restrict__ b1) {
    __shared__ float t[HH];
    const int f = blockIdx.x, h = threadIdx.x;
    float w = w1[f * HH + h], b = b1[f * HH + h];
    float tv;
    if (w == 0.f) tv = finf();
    else { tv = -b / w; if (tv != tv) tv = finf(); }
    t[h] = tv;
    __syncthreads();
    for (int p = 0; p < HH; ++p) {          // odd-even transposition sort
        int i = 2 * h + (p & 1);
        if (i + 1 < HH) {
            float a = t[i], c = t[i + 1];
            if (c < a) { t[i] = c; t[i + 1] = a; }
        }
        __syncthreads();
    }
    g_tsort[f * HH + h] = t[h];
}

// ---- K1: per (feature f, L1-segment s): in-segment kinks + prefix slopes ----
__global__ void build_kernel(const float* __restrict__ w1, const float* __restrict__ b1,
                             const float* __restrict__ w2, const float* __restrict__ b2,
                             const float* __restrict__ w3, const float* __restrict__ b3) {
    const int s = blockIdx.x;   // 0..64
    const int f = blockIdx.y;
    const int g = threadIdx.x;  // 0..63
    __shared__ float w1s[HH], b1s[HH];
    __shared__ float kk[HH], dsv[HH], div_[HH];
    __shared__ double red[HH], ps[HH], pi[HH];
    __shared__ float Ts[HH + 2];
    __shared__ double sS0, sI0;

    w1s[g] = w1[f * HH + g];
    b1s[g] = b1[f * HH + g];
    Ts[g + 1] = g_tsort[f * HH + g];
    if (g == 0) { Ts[0] = -finf(); Ts[HH + 1] = finf(); }
    __syncthreads();

    const float Tlo = Ts[s], Thi = Ts[s + 1];
    const bool loI = isinf(Tlo), hiI = isinf(Thi);
    float xm;
    if (!loI && !hiI)      xm = 0.5f * Tlo + 0.5f * Thi;
    else if (loI && hiI)   xm = 0.f;
    else if (loI)          xm = Thi - 1.f;
    else                   xm = Tlo + 1.f;

    // alpha_g, beta'_g for this segment (active set fixed within segment)
    float a = 0.f, be = 0.f;
    #pragma unroll 8
    for (int h = 0; h < HH; ++h) {
        if (fmaf(xm, w1s[h], b1s[h]) > 0.f) {   // uniform branch over block
            float w2v = __ldg(w2 + f * HH * HH + h * HH + g);
            a  = fmaf(w1s[h], w2v, a);
            be = fmaf(b1s[h], w2v, be);
        }
    }
    be += __ldg(b2 + f * HH + g);
    const float w3v = __ldg(w3 + f * HH + g);

    // classify relu_g within (Tlo, Thi)
    bool ev = false, baseAct = false;
    float kink = finf(), dsl = 0.f, din = 0.f;
    if (a > 0.f) {
        float xs = -be / a;
        if (xs <= Tlo) baseAct = true;                       // active throughout
        else if (xs < Thi) { ev = true; kink = xs; dsl = w3v * a; din = w3v * be; }
    } else if (a < 0.f) {
        float xs = -be / a;
        if (xs >= Thi) baseAct = true;                       // active throughout
        else if (xs > Tlo) { ev = true; baseAct = true;      // active at start, turns off
                             kink = xs; dsl = -w3v * a; din = -w3v * be; }
    } else {
        if (be > 0.f) baseAct = true;                        // constant contribution
    }

    // S0 = sum of active w3*alpha at segment start (fp64 reduce)
    red[g] = baseAct ? (double)(w3v * a) : 0.0;
    __syncthreads();
    for (int o = 32; o > 0; o >>= 1) { if (g < o) red[g] += red[g + o]; __syncthreads(); }
    if (g == 0) sS0 = red[0];
    __syncthreads();
    red[g] = baseAct ? (double)(w3v * be) : 0.0;
    __syncthreads();
    for (int o = 32; o > 0; o >>= 1) { if (g < o) red[g] += red[g + o]; __syncthreads(); }
    if (g == 0) sI0 = red[0] + (double)__ldg(b3 + f);        // fold b3 into intercept
    const int n = __syncthreads_count(ev ? 1 : 0);

    kk[g] = kink; dsv[g] = dsl; div_[g] = din;
    __syncthreads();

    // bitonic sort 64 (keys kk asc; non-events padded +inf)
    for (int k = 2; k <= HH; k <<= 1)
        for (int j = k >> 1; j > 0; j >>= 1) {
            int ixj = g ^ j;
            if (ixj > g) {
                bool up = ((g & k) == 0);
                if ((kk[g] > kk[ixj]) == up) {
                    float t0;
                    t0 = kk[g];   kk[g] = kk[ixj];     kk[ixj] = t0;
                    t0 = dsv[g];  dsv[g] = dsv[ixj];   dsv[ixj] = t0;
                    t0 = div_[g]; div_[g] = div_[ixj]; div_[ixj] = t0;
                }
            }
            __syncthreads();
        }

    // inclusive prefix sums of deltas (fp64)
    ps[g] = (double)dsv[g]; pi[g] = (double)div_[g];
    __syncthreads();
    for (int o = 1; o < HH; o <<= 1) {
        double vs = (g >= o) ? ps[g - o] : 0.0;
        double vi = (g >= o) ? pi[g - o] : 0.0;
        __syncthreads();
        ps[g] += vs; pi[g] += vi;
        __syncthreads();
    }

    const int fs = f * 65 + s;
    if (g == 0) {
        stage_n[fs] = n;
        stage_SI[fs * 65] = make_float2((float)sS0, (float)sI0);
    }
    if (g < n) {
        stage_kinks[fs * 64 + g] = kk[g];
        stage_SI[fs * 65 + g + 1] =
            make_float2((float)(sS0 + ps[g]), (float)(sI0 + pi[g]));
    }
}

// ---- K2: concatenate per-segment tables (naturally globally sorted) ----
__global__ void compact_kernel() {
    const int f = blockIdx.x;
    const int tid = threadIdx.x;
    __shared__ int offX[66];
    __shared__ int nsh[65];
    if (tid < 65) nsh[tid] = stage_n[f * 65 + tid];
    __syncthreads();
    if (tid == 0) {
        int c = 0;
        for (int s = 0; s < 65; ++s) { offX[s] = c; c += nsh[s] + (s < 64 ? 1 : 0); }
        offX[65] = c;
        g_N[f] = c;
    }
    __syncthreads();
    for (int s = 0; s < 65; ++s) {
        const int n = nsh[s], ox = offX[s], fs = f * 65 + s;
        for (int j = tid; j < n; j += blockDim.x)
            g_X[f * NMAX + ox + j] = stage_kinks[fs * 64 + j];
        for (int j = tid; j <= n; j += blockDim.x)
            g_SI[f * (NMAX + 1) + ox + j] = stage_SI[fs * 65 + j];
        if (s < 64 && tid == 0)
            g_X[f * NMAX + ox + n] = g_tsort[f * HH + s];
    }
}

// ---- K3: transpose x (B,F) -> (F,B) for coalesced eval ----
__global__ void xT_kernel(const float* __restrict__ x) {
    __shared__ float tile[32][33];
    const int bb = blockIdx.x * 32, ff = blockIdx.y * 32;
    const int tx = threadIdx.x, ty = threadIdx.y;
    #pragma unroll
    for (int i = ty; i < 32; i += 8)
        tile[i][tx] = x[(size_t)(bb + i) * FF + ff + tx];
    __syncthreads();
    #pragma unroll
    for (int i = ty; i < 32; i += 8)
        g_xT[(size_t)(ff + i) * BB + bb + tx] = tile[tx][i];
}

// ---- K4: eval — binary search + 1 FMA per (b,f) ----
__global__ __launch_bounds__(256) void eval_kernel() {
    __shared__ float Xs[NMAX];
    const int f = blockIdx.y;
    const int N = g_N[f];
    for (int i = threadIdx.x; i < N; i += 256) Xs[i] = g_X[f * NMAX + i];
    __syncthreads();
    const float2* SI = g_SI + (size_t)f * (NMAX + 1);
    const float* xp = g_xT + (size_t)f * BB + blockIdx.x * 4096;
    float* cp = g_contrib + (size_t)f * BB + blockIdx.x * 4096;
    for (int r = threadIdx.x; r < 4096; r += 256) {
        float xv = __ldg(xp + r);
        int lo = 0, len = N;
        while (len > 0) {                       // upper_bound
            int half = len >> 1;
            if (Xs[lo + half] <= xv) { lo += half + 1; len -= half + 1; }
            else len = half;
        }
        float2 si = __ldg(SI + lo);
        cp[r] = fmaf(si.x, xv, si.y);
    }
}

// ---- K5: finalize (proven from earlier rounds) ----
__global__ void finalize_kernel(const float* __restrict__ bias,
                                float* __restrict__ out) {
    int b = blockIdx.x * blockDim.x + threadIdx.x;
    if (b >= BB) return;
    float l = bias[0];
    #pragma unroll 16
    for (int f = 0; f < FF; ++f) l += g_contrib[f * BB + b];
    float p = 1.0f / (1.0f + expf(-l));
    out[2 * b + 0] = 1.0f - p;
    out[2 * b + 1] = p;
}

extern "C" void kernel_launch(void* const* d_in, const int* in_sizes, int n_in,
                              void* d_out, int out_size) {
    const float* x    = (const float*)d_in[0];
    const float* w1   = (const float*)d_in[1];
    const float* b1   = (const float*)d_in[2];
    const float* w2   = (const float*)d_in[3];
    const float* b2   = (const float*)d_in[4];
    const float* w3   = (const float*)d_in[5];
    const float* b3   = (const float*)d_in[6];
    const float* bias = (const float*)d_in[7];
    float* out = (float*)d_out;

    sort_t_kernel<<<FF, HH>>>(w1, b1);
    build_kernel<<<dim3(65, FF), HH>>>(w1, b1, w2, b2, w3, b3);
    compact_kernel<<<FF, 256>>>();
    xT_kernel<<<dim3(BB / 32, FF / 32), dim3(32, 8)>>>(x);
    eval_kernel<<<dim3(8, FF), 256>>>();
    finalize_kernel<<<BB / 256, 256>>>(bias, out);
}

// round 10
// speedup vs baseline: 3.1207x; 1.0028x over previous
#include <cuda_runtime.h>
#include <cstdint>

#define BB 32768
#define FF 128
#define HH 64
#define NMAX 4224   // 64 L1 boundaries + 65*64 L2 kinks (worst case)
#define NB 4096     // eval bucket count
#define XLO (-5.5f)
#define XHI (5.5f)

// ---- device scratch (no cudaMalloc allowed) ----
__device__ float  g_tsort[FF * HH];
__device__ int    stage_n[FF * 65];
__device__ float  stage_kinks[FF * 65 * 64];
__device__ float2 stage_SI[FF * 65 * 65];
__device__ float  g_X[FF * NMAX];
__device__ float2 g_SI[FF * (NMAX + 1)];
__device__ int    g_N[FF];
__device__ uint16_t g_bstart[FF * NB];
__device__ float  g_xT[FF * BB];
__device__ float  g_contrib[FF * BB];

__device__ __forceinline__ float finf() { return __int_as_float(0x7f800000); }

// ---- K0: per-feature sorted layer-1 breakpoints t_h = -b1/w1 ----
__global__ void sort_t_kernel(const float* __restrict__ w1, const float* __restrict__ b1) {
    __shared__ float t[HH];
    const int f = blockIdx.x, h = threadIdx.x;
    float w = w1[f * HH + h], b = b1[f * HH + h];
    float tv;
    if (w == 0.f) tv = finf();
    else { tv = -b / w; if (tv != tv) tv = finf(); }
    t[h] = tv;
    __syncthreads();
    for (int p = 0; p < HH; ++p) {          // odd-even transposition sort
        int i = 2 * h + (p & 1);
        if (i + 1 < HH) {
            float a = t[i], c = t[i + 1];
            if (c < a) { t[i] = c; t[i + 1] = a; }
        }
        __syncthreads();
    }
    g_tsort[f * HH + h] = t[h];
}

// ---- K1: per (feature f, L1-segment s): in-segment kinks + prefix slopes ----
__global__ void build_kernel(const float* __restrict__ w1, const float* __restrict__ b1,
                             const float* __restrict__ w2, const float* __restrict__ b2,
                             const float* __restrict__ w3, const float* __restrict__ b3) {
    const int s = blockIdx.x;   // 0..64
    const int f = blockIdx.y;
    const int g = threadIdx.x;  // 0..63
    __shared__ float w1s[HH], b1s[HH];
    __shared__ float kk[HH], dsv[HH], div_[HH];
    __shared__ double red[HH], ps[HH], pi[HH];
    __shared__ float Ts[HH + 2];
    __shared__ double sS0, sI0;

    w1s[g] = w1[f * HH + g];
    b1s[g] = b1[f * HH + g];
    Ts[g + 1] = g_tsort[f * HH + g];
    if (g == 0) { Ts[0] = -finf(); Ts[HH + 1] = finf(); }
    __syncthreads();

    const float Tlo = Ts[s], Thi = Ts[s + 1];
    const bool loI = isinf(Tlo), hiI = isinf(Thi);
    float xm;
    if (!loI && !hiI)      xm = 0.5f * Tlo + 0.5f * Thi;
    else if (loI && hiI)   xm = 0.f;
    else if (loI)          xm = Thi - 1.f;
    else                   xm = Tlo + 1.f;

    // alpha_g, beta'_g for this segment (active set fixed within segment)
    float a = 0.f, be = 0.f;
    #pragma unroll 8
    for (int h = 0; h < HH; ++h) {
        if (fmaf(xm, w1s[h], b1s[h]) > 0.f) {   // uniform branch over block
            float w2v = __ldg(w2 + f * HH * HH + h * HH + g);
            a  = fmaf(w1s[h], w2v, a);
            be = fmaf(b1s[h], w2v, be);
        }
    }
    be += __ldg(b2 + f * HH + g);
    const float w3v = __ldg(w3 + f * HH + g);

    // classify relu_g within (Tlo, Thi)
    bool ev = false, baseAct = false;
    float kink = finf(), dsl = 0.f, din = 0.f;
    if (a > 0.f) {
        float xs = -be / a;
        if (xs <= Tlo) baseAct = true;
        else if (xs < Thi) { ev = true; kink = xs; dsl = w3v * a; din = w3v * be; }
    } else if (a < 0.f) {
        float xs = -be / a;
        if (xs >= Thi) baseAct = true;
        else if (xs > Tlo) { ev = true; baseAct = true;
                             kink = xs; dsl = -w3v * a; din = -w3v * be; }
    } else {
        if (be > 0.f) baseAct = true;
    }

    // S0/I0 at segment start (fp64 reduce)
    red[g] = baseAct ? (double)(w3v * a) : 0.0;
    __syncthreads();
    for (int o = 32; o > 0; o >>= 1) { if (g < o) red[g] += red[g + o]; __syncthreads(); }
    if (g == 0) sS0 = red[0];
    __syncthreads();
    red[g] = baseAct ? (double)(w3v * be) : 0.0;
    __syncthreads();
    for (int o = 32; o > 0; o >>= 1) { if (g < o) red[g] += red[g + o]; __syncthreads(); }
    if (g == 0) sI0 = red[0] + (double)__ldg(b3 + f);
    const int n = __syncthreads_count(ev ? 1 : 0);

    kk[g] = kink; dsv[g] = dsl; div_[g] = din;
    __syncthreads();

    // bitonic sort 64 (keys kk asc; non-events padded +inf)
    for (int k = 2; k <= HH; k <<= 1)
        for (int j = k >> 1; j > 0; j >>= 1) {
            int ixj = g ^ j;
            if (ixj > g) {
                bool up = ((g & k) == 0);
                if ((kk[g] > kk[ixj]) == up) {
                    float t0;
                    t0 = kk[g];   kk[g] = kk[ixj];     kk[ixj] = t0;
                    t0 = dsv[g];  dsv[g] = dsv[ixj];   dsv[ixj] = t0;
                    t0 = div_[g]; div_[g] = div_[ixj]; div_[ixj] = t0;
                }
            }
            __syncthreads();
        }

    // inclusive prefix sums of deltas (fp64)
    ps[g] = (double)dsv[g]; pi[g] = (double)div_[g];
    __syncthreads();
    for (int o = 1; o < HH; o <<= 1) {
        double vs = (g >= o) ? ps[g - o] : 0.0;
        double vi = (g >= o) ? pi[g - o] : 0.0;
        __syncthreads();
        ps[g] += vs; pi[g] += vi;
        __syncthreads();
    }

    const int fs = f * 65 + s;
    if (g == 0) {
        stage_n[fs] = n;
        stage_SI[fs * 65] = make_float2((float)sS0, (float)sI0);
    }
    if (g < n) {
        stage_kinks[fs * 64 + g] = kk[g];
        stage_SI[fs * 65 + g + 1] =
            make_float2((float)(sS0 + ps[g]), (float)(sI0 + pi[g]));
    }
}

// ---- K2: concatenate per-segment tables (naturally globally sorted) ----
__global__ void compact_kernel() {
    const int f = blockIdx.x;
    const int tid = threadIdx.x;
    __shared__ int offX[66];
    __shared__ int nsh[65];
    if (tid < 65) nsh[tid] = stage_n[f * 65 + tid];
    __syncthreads();
    if (tid == 0) {
        int c = 0;
        for (int s = 0; s < 65; ++s) { offX[s] = c; c += nsh[s] + (s < 64 ? 1 : 0); }
        offX[65] = c;
        g_N[f] = c;
    }
    __syncthreads();
    for (int s = 0; s < 65; ++s) {
        const int n = nsh[s], ox = offX[s], fs = f * 65 + s;
        for (int j = tid; j < n; j += blockDim.x)
            g_X[f * NMAX + ox + j] = stage_kinks[fs * 64 + j];
        for (int j = tid; j <= n; j += blockDim.x)
            g_SI[f * (NMAX + 1) + ox + j] = stage_SI[fs * 65 + j];
        if (s < 64 && tid == 0)
            g_X[f * NMAX + ox + n] = g_tsort[f * HH + s];
    }
}

// ---- K2b: per-feature uniform-grid bucket table (lower_bound starts) ----
__global__ __launch_bounds__(256) void bucket_kernel() {
    __shared__ float Xs[NMAX];
    const int f = blockIdx.x;
    const int N = g_N[f];
    for (int i = threadIdx.x; i < N; i += 256) Xs[i] = g_X[f * NMAX + i];
    __syncthreads();
    const float inv = (XHI - XLO) / (float)NB;
    for (int i = threadIdx.x; i < NB; i += 256) {
        float bl = XLO + (float)i * inv;
        int lo = 0, len = N;
        while (len > 0) {                    // lower_bound: first idx with X >= bl
            int half = len >> 1;
            if (Xs[lo + half] < bl) { lo += half + 1; len -= half + 1; }
            else len = half;
        }
        g_bstart[f * NB + i] = (uint16_t)lo;
    }
}

// ---- K3: transpose x (B,F) -> (F,B) for coalesced eval ----
__global__ void xT_kernel(const float* __restrict__ x) {
    __shared__ float tile[32][33];
    const int bb = blockIdx.x * 32, ff = blockIdx.y * 32;
    const int tx = threadIdx.x, ty = threadIdx.y;
    #pragma unroll
    for (int i = ty; i < 32; i += 8)
        tile[i][tx] = x[(size_t)(bb + i) * FF + ff + tx];
    __syncthreads();
    #pragma unroll
    for (int i = ty; i < 32; i += 8)
        g_xT[(size_t)(ff + i) * BB + bb + tx] = tile[tx][i];
}

// ---- K4: eval — bucket lookup + short fix-up scan + 1 FMA per (b,f) ----
__global__ __launch_bounds__(256) void eval_kernel() {
    __shared__ float Xs[NMAX];
    __shared__ uint16_t bs[NB];
    const int f = blockIdx.y;
    const int N = g_N[f];
    for (int i = threadIdx.x; i < N; i += 256) Xs[i] = g_X[f * NMAX + i];
    {
        const uint32_t* src = (const uint32_t*)(g_bstart + f * NB);
        uint32_t* dst = (uint32_t*)bs;
        for (int i = threadIdx.x; i < NB / 2; i += 256) dst[i] = src[i];
    }
    __syncthreads();
    const float scale = (float)NB / (XHI - XLO);
    const float2* SI = g_SI + (size_t)f * (NMAX + 1);
    const float* xp = g_xT + (size_t)f * BB + blockIdx.x * 4096;
    float* cp = g_contrib + (size_t)f * BB + blockIdx.x * 4096;
    for (int r = threadIdx.x; r < 4096; r += 256) {
        float xv = __ldg(xp + r);
        int k = (int)((xv - XLO) * scale);
        k = max(0, min(NB - 1, k));
        int idx = bs[k];
        // bidirectional fix-up -> exact upper_bound (robust to bucket rounding)
        while (idx > 0 && Xs[idx - 1] > xv) --idx;
        while (idx < N && Xs[idx] <= xv) ++idx;
        float2 si = __ldg(SI + idx);
        cp[r] = fmaf(si.x, xv, si.y);
    }
}

// ---- K5: finalize ----
__global__ void finalize_kernel(const float* __restrict__ bias,
                                float* __restrict__ out) {
    int b = blockIdx.x * blockDim.x + threadIdx.x;
    if (b >= BB) return;
    float l = bias[0];
    #pragma unroll 16
    for (int f = 0; f < FF; ++f) l += g_contrib[f * BB + b];
    float p = 1.0f / (1.0f + expf(-l));
    out[2 * b + 0] = 1.0f - p;
    out[2 * b + 1] = p;
}

extern "C" void kernel_launch(void* const* d_in, const int* in_sizes, int n_in,
                              void* d_out, int out_size) {
    const float* x    = (const float*)d_in[0];
    const float* w1   = (const float*)d_in[1];
    const float* b1   = (const float*)d_in[2];
    const float* w2   = (const float*)d_in[3];
    const float* b2   = (const float*)d_in[4];
    const float* w3   = (const float*)d_in[5];
    const float* b3   = (const float*)d_in[6];
    const float* bias = (const float*)d_in[7];
    float* out = (float*)d_out;

    sort_t_kernel<<<FF, HH>>>(w1, b1);
    build_kernel<<<dim3(65, FF), HH>>>(w1, b1, w2, b2, w3, b3);
    compact_kernel<<<FF, 256>>>();
    bucket_kernel<<<FF, 256>>>();
    xT_kernel<<<dim3(BB / 32, FF / 32), dim3(32, 8)>>>(x);
    eval_kernel<<<dim3(8, FF), 256>>>();
    finalize_kernel<<<BB / 256, 256>>>(bias, out);
}